// round 1
// baseline (speedup 1.0000x reference)
#include <cuda_runtime.h>
#include <math.h>

#define BATCH 32768
#define NA 9
#define NR 4
#define TB 8
#define ROWS (TB*NA)
#define KT 16
#define LRS 0.2f
#define BN_EPS 1e-5f

// Scratch: raw (pre-BN) block outputs + BN statistic accumulators
__device__ float g_h0[BATCH*NA*64];
__device__ float g_h1[BATCH*NA*128];
__device__ float g_h2[BATCH*NA*256];
__device__ float g_stats[3][2][16];   // [block][sum/sumsq][atom(padded)]

__global__ void zero_stats_kernel() {
    int i = threadIdx.x;
    if (i < 3*2*16) ((float*)g_stats)[i] = 0.0f;
}

// One RGCN block:
//   X = [h_norm | adj_r @ h_norm (r=0..3)]  ([72 x 5*DIN] per CTA, in SMEM)
//   out_raw = X @ [Ws; Wr] + bias           (register-tiled SMEM GEMM)
//   accumulate per-atom sum/sumsq of out_raw into g_stats[SIDX_OUT]
// NORM: input is previous block's raw output -> apply BN(prev stats)+affine+LeakyReLU on load.
template<int DIN, int DOUT, bool NORM, int SIDX_IN, int SIDX_OUT>
__global__ void __launch_bounds__(256) rgcn_block_kernel(
    const float* __restrict__ hin,    // [B,9,DIN] (raw prev output, or atom_feats)
    const float* __restrict__ adj,    // [B,4,9,9]
    const float* __restrict__ ws,     // [DIN,DOUT]
    const float* __restrict__ wr,     // [4*DIN,DOUT] (flattened [4,DIN,DOUT])
    const float* __restrict__ bias,   // [DOUT]
    const float* __restrict__ gamma,  // [9]  BN affine of PREVIOUS block
    const float* __restrict__ beta,   // [9]
    float* __restrict__ hout,         // [B,9,DOUT] raw
    float inv_count_prev)             // 1/(B*DIN)
{
    constexpr int K  = 5*DIN;
    constexpr int KP = ((K + KT - 1)/KT)*KT;
    constexpr int CPT = DOUT/32;

    extern __shared__ float smem[];
    float* xs    = smem;                      // ROWS*KP
    float* adj_s = xs + ROWS*KP;              // TB*4*81 = 2592
    float* wt    = adj_s + TB*NR*NA*NA;       // KT*DOUT
    float* red   = wt + KT*DOUT;              // 32 (sum[0..8], sq[16..24])
    float* nrm   = red + 32;                  // 32 (a[0..8], c[16..24])

    const int tid = threadIdx.x;
    const int ty  = tid >> 5;     // local batch (warp id)
    const int tx  = tid & 31;     // column lane
    const int bBase = blockIdx.x * TB;

    if (tid < 32) red[tid] = 0.0f;
    if (NORM && tid < NA) {
        float s = g_stats[SIDX_IN][0][tid];
        float q = g_stats[SIDX_IN][1][tid];
        float mean = s * inv_count_prev;
        float var  = q * inv_count_prev - mean*mean;
        float a = rsqrtf(var + BN_EPS) * gamma[tid];
        nrm[tid]    = a;
        nrm[16+tid] = beta[tid] - mean*a;
    }
    for (int i = tid; i < TB*NR*NA*NA; i += 256)
        adj_s[i] = adj[(size_t)bBase*(NR*NA*NA) + i];
    __syncthreads();

    // Load h (normalized+activated if NORM) into xs[:, 0:DIN]
    for (int i = tid; i < TB*NA*DIN; i += 256) {
        float v = hin[(size_t)bBase*(NA*DIN) + i];
        int row = i / DIN;
        int d   = i - row*DIN;
        if (NORM) {
            int n = row % NA;
            v = fmaf(v, nrm[n], nrm[16+n]);
            v = v > 0.f ? v : LRS*v;
        }
        xs[row*KP + d] = v;
    }
    if (KP > K) {  // zero-pad tail columns (block0 only)
        for (int i = tid; i < ROWS*(KP-K); i += 256) {
            int row = i/(KP-K);
            xs[row*KP + K + (i - row*(KP-K))] = 0.f;
        }
    }
    __syncthreads();

    // ah[bl,r,n,d] = sum_m adj[bl,r,n,m] * h[bl,m,d]  -> xs[:, DIN+r*DIN+d]
    for (int i = tid; i < TB*NR*NA*DIN; i += 256) {
        int d = i % DIN;
        int t = i / DIN;
        int n = t % NA; t /= NA;
        int r = t & 3; int bl = t >> 2;
        const float* arow = &adj_s[((bl*NR + r)*NA + n)*NA];
        const float* xcol = &xs[(bl*NA)*KP + d];
        float acc = 0.f;
        #pragma unroll
        for (int m = 0; m < NA; m++) acc = fmaf(arow[m], xcol[m*KP], acc);
        xs[(bl*NA + n)*KP + DIN + r*DIN + d] = acc;
    }
    // (loop-top __syncthreads below covers this write before GEMM reads)

    // GEMM: thread owns 9 rows (its batch) x CPT columns (tx + 32*j)
    float acc[NA][CPT];
    #pragma unroll
    for (int i=0;i<NA;i++)
        #pragma unroll
        for (int j=0;j<CPT;j++) acc[i][j]=0.f;

    const int rowBase = ty*NA;
    for (int k0 = 0; k0 < KP; k0 += KT) {
        __syncthreads();
        for (int i = tid; i < KT*DOUT; i += 256) {
            int kk = i / DOUT;
            int e  = i - kk*DOUT;
            int k  = k0 + kk;
            float w = 0.f;
            if (k < K) w = (k < DIN) ? ws[k*DOUT + e] : wr[(k-DIN)*DOUT + e];
            wt[i] = w;
        }
        __syncthreads();
        #pragma unroll
        for (int kk = 0; kk < KT; kk++) {
            float xv[NA];
            #pragma unroll
            for (int i=0;i<NA;i++) xv[i] = xs[(rowBase+i)*KP + k0 + kk];  // warp broadcast
            #pragma unroll
            for (int j=0;j<CPT;j++) {
                float w = wt[kk*DOUT + tx + 32*j];                        // conflict-free
                #pragma unroll
                for (int i=0;i<NA;i++) acc[i][j] = fmaf(xv[i], w, acc[i][j]);
            }
        }
    }

    float bia[CPT];
    #pragma unroll
    for (int j=0;j<CPT;j++) bia[j] = bias[tx + 32*j];

    #pragma unroll
    for (int i=0;i<NA;i++) {
        size_t rb = ((size_t)(bBase+ty)*NA + i)*DOUT;
        float s=0.f, q=0.f;
        #pragma unroll
        for (int j=0;j<CPT;j++) {
            float v = acc[i][j] + bia[j];
            hout[rb + tx + 32*j] = v;
            s += v; q = fmaf(v, v, q);
        }
        atomicAdd(&red[i],    s);
        atomicAdd(&red[16+i], q);
    }
    __syncthreads();
    if (tid < NA) {
        atomicAdd(&g_stats[SIDX_OUT][0][tid], red[tid]);
        atomicAdd(&g_stats[SIDX_OUT][1][tid], red[16+tid]);
    }
}

// BN(block2) + affine + LeakyReLU + masked atom-sum + FC. One warp per batch.
__global__ void __launch_bounds__(256) readout_kernel(
    const float* __restrict__ mask,
    const float* __restrict__ fcw,    // [256]
    const float* __restrict__ fcb,    // [1]
    const float* __restrict__ gamma,  // g2
    const float* __restrict__ beta,   // be2
    float* __restrict__ out,          // [B]
    float inv_count)
{
    __shared__ float a_s[NA], c_s[NA], fcs[256];
    int tid = threadIdx.x;
    if (tid < NA) {
        float s = g_stats[2][0][tid];
        float q = g_stats[2][1][tid];
        float mean = s*inv_count;
        float var  = q*inv_count - mean*mean;
        float a = rsqrtf(var + BN_EPS)*gamma[tid];
        a_s[tid] = a;
        c_s[tid] = beta[tid] - mean*a;
    }
    fcs[tid] = fcw[tid];
    __syncthreads();

    int lane = tid & 31, w = tid >> 5;
    int b = blockIdx.x*8 + w;
    float accv = 0.f;
    #pragma unroll
    for (int n=0;n<NA;n++) {
        float mk = mask[b*NA + n];
        const float* hp = &g_h2[((size_t)b*NA + n)*256];
        float aa = a_s[n], cc = c_s[n];
        #pragma unroll
        for (int j=0;j<8;j++) {
            int e = lane + 32*j;
            float v = fmaf(hp[e], aa, cc);
            v = v > 0.f ? v : LRS*v;
            accv = fmaf(v*mk, fcs[e], accv);
        }
    }
    #pragma unroll
    for (int o=16;o>0;o>>=1) accv += __shfl_xor_sync(0xffffffffu, accv, o);
    if (lane==0) out[b] = accv + fcb[0];
}

extern "C" void kernel_launch(void* const* d_in, const int* in_sizes, int n_in,
                              void* d_out, int out_size)
{
    const float* atom = (const float*)d_in[0];
    const float* adj  = (const float*)d_in[1];
    const float* mask = (const float*)d_in[2];
    const float* ws0=(const float*)d_in[3],  *wr0=(const float*)d_in[4],  *b0=(const float*)d_in[5],  *g0=(const float*)d_in[6],  *be0=(const float*)d_in[7];
    const float* ws1=(const float*)d_in[8],  *wr1=(const float*)d_in[9],  *b1=(const float*)d_in[10], *g1=(const float*)d_in[11], *be1=(const float*)d_in[12];
    const float* ws2=(const float*)d_in[13], *wr2=(const float*)d_in[14], *b2=(const float*)d_in[15], *g2=(const float*)d_in[16], *be2=(const float*)d_in[17];
    const float* fcw=(const float*)d_in[18], *fcb=(const float*)d_in[19];
    float* out = (float*)d_out;

    float *h0, *h1, *h2;
    cudaGetSymbolAddress((void**)&h0, g_h0);
    cudaGetSymbolAddress((void**)&h1, g_h1);
    cudaGetSymbolAddress((void**)&h2, g_h2);

    // dynamic smem sizes (floats): ROWS*KP + 2592 + KT*DOUT + 64
    const int smem0 = (ROWS*32  + 2592 + KT*64  + 64)*4;   //  ~24 KB
    const int smem1 = (ROWS*320 + 2592 + KT*128 + 64)*4;   // ~111 KB
    const int smem2 = (ROWS*640 + 2592 + KT*256 + 64)*4;   // ~211 KB

    cudaFuncSetAttribute((const void*)rgcn_block_kernel<64,128,true,0,1>,
                         cudaFuncAttributeMaxDynamicSharedMemorySize, smem1);
    cudaFuncSetAttribute((const void*)rgcn_block_kernel<128,256,true,1,2>,
                         cudaFuncAttributeMaxDynamicSharedMemorySize, smem2);

    const int grid = BATCH/TB;   // 4096

    zero_stats_kernel<<<1,128>>>();
    rgcn_block_kernel<5,64,false,0,0><<<grid,256,smem0>>>(
        atom, adj, ws0, wr0, b0, g0, be0, h0, 0.f);
    rgcn_block_kernel<64,128,true,0,1><<<grid,256,smem1>>>(
        h0, adj, ws1, wr1, b1, g0, be0, h1, 1.0f/((float)BATCH*64.0f));
    rgcn_block_kernel<128,256,true,1,2><<<grid,256,smem2>>>(
        h1, adj, ws2, wr2, b2, g1, be1, h2, 1.0f/((float)BATCH*128.0f));
    readout_kernel<<<grid,256>>>(
        mask, fcw, fcb, g2, be2, out, 1.0f/((float)BATCH*256.0f));
}

// round 2
// speedup vs baseline: 1.3146x; 1.3146x over previous
#include <cuda_runtime.h>
#include <math.h>

#define BATCH 32768
#define NA 9
#define NR 4
#define TB 8
#define ROWS (TB*NA)
#define LRS 0.2f
#define BN_EPS 1e-5f

typedef unsigned long long ull;

// Scratch: raw (pre-BN) block outputs + BN statistic accumulators
__device__ float g_h0[(size_t)BATCH*NA*64];
__device__ float g_h1[(size_t)BATCH*NA*128];
__device__ float g_h2[(size_t)BATCH*NA*256];
__device__ float g_stats[3][2][16];   // [block][sum/sumsq][atom(padded)]

__global__ void zero_stats_kernel() {
    int i = threadIdx.x;
    if (i < 96) ((float*)g_stats)[i] = 0.0f;
}

// ---- f32x2 packed helpers (sm_103a FFMA2 path) ----
__device__ __forceinline__ ull pk2(float v) {
    ull r; unsigned u = __float_as_uint(v);
    asm("mov.b64 %0,{%1,%1};" : "=l"(r) : "r"(u)); return r;
}
__device__ __forceinline__ ull pk2f(float a, float b) {
    ull r;
    asm("mov.b64 %0,{%1,%2};" : "=l"(r)
        : "r"(__float_as_uint(a)), "r"(__float_as_uint(b)));
    return r;
}
__device__ __forceinline__ void up2(ull v, float& a, float& b) {
    unsigned x, y;
    asm("mov.b64 {%0,%1},%2;" : "=r"(x), "=r"(y) : "l"(v));
    a = __uint_as_float(x); b = __uint_as_float(y);
}
__device__ __forceinline__ void fma2(ull& d, ull a, ull b) {
    asm("fma.rn.f32x2 %0,%1,%2,%0;" : "+l"(d) : "l"(a), "l"(b));
}

// One RGCN block, restructured:  out = bias + h@Ws + Sum_r adj_r @ (h@Wr_r)
// CTA: TB=8 batches (warp=batch), CT output columns (lane owns CT/64 f32x2 pairs).
// h tile lives in smem; weight tiles double-buffered; adj applied in registers.
// NORM: apply BN(prev stats)+affine+LeakyReLU on h load.
template<int DIN, int DOUT, int CT, int KT, bool NORM, int SIN, int SOUT>
__global__ void __launch_bounds__(256, 2) rgcn_v2(
    const float* __restrict__ hin,    // [B,9,DIN]
    const float* __restrict__ adj,    // [B,4,9,9]
    const float* __restrict__ ws,     // [DIN,DOUT]
    const float* __restrict__ wr,     // [4,DIN,DOUT]
    const float* __restrict__ bias,   // [DOUT]
    const float* __restrict__ gamma,  // [9] prev-block BN affine
    const float* __restrict__ beta,   // [9]
    float* __restrict__ hout,         // [B,9,DOUT] raw
    float invp)
{
    constexpr int CPT = CT / 64;      // f32x2 pairs per lane
    constexpr int NCH = DIN / KT;     // k-chunks per weight matrix
    constexpr int C5  = 5 * NCH;      // total chunks (Ws, Wr0..Wr3)

    extern __shared__ float sm[];
    float* x_s   = sm;                       // ROWS*DIN
    float* adj_s = x_s + ROWS*DIN;           // TB*4*81
    float* wt    = adj_s + TB*NR*NA*NA;      // 2*KT*CT (double buffer)
    __shared__ float red[32];
    __shared__ float nrm[32];

    const int tid = threadIdx.x;
    const int wq  = tid >> 5;                // local batch
    const int tx  = tid & 31;
    const int bBase = blockIdx.x * TB;
    const int cbase = blockIdx.y * CT;

    if (tid < 32) red[tid] = 0.0f;
    if (NORM && tid < NA) {
        float s = g_stats[SIN][0][tid];
        float q = g_stats[SIN][1][tid];
        float mean = s * invp;
        float var  = q * invp - mean * mean;
        float a = rsqrtf(var + BN_EPS) * gamma[tid];
        nrm[tid]      = a;
        nrm[16 + tid] = beta[tid] - mean * a;
    }
    for (int i = tid; i < TB*NR*NA*NA; i += 256)
        adj_s[i] = adj[(size_t)bBase*NR*NA*NA + i];
    __syncthreads();

    // h tile (normalized + activated if NORM)
    for (int i = tid; i < ROWS*DIN; i += 256) {
        float v = hin[(size_t)bBase*NA*DIN + i];
        if (NORM) {
            int n = (i / DIN) % NA;
            v = fmaf(v, nrm[n], nrm[16 + n]);
            v = v > 0.f ? v : LRS * v;
        }
        x_s[i] = v;
    }

    // weight chunk staging (chunk c covers matrix c/NCH, rows [(c%NCH)*KT, +KT))
    auto stage = [&](int c, int buf) {
        const int mat = c / NCH, k0 = (c % NCH) * KT;
        const float* W = (mat == 0) ? ws : wr + (size_t)(mat - 1)*DIN*DOUT;
        constexpr int NV = (KT * CT) / 4;
        #pragma unroll 4
        for (int i = tid; i < NV; i += 256) {
            int row = i / (CT/4), cv = i - row*(CT/4);
            float4 v = *(const float4*)&W[(size_t)(k0 + row)*DOUT + cbase + 4*cv];
            *(float4*)&wt[buf*KT*CT + row*CT + 4*cv] = v;
        }
    };
    stage(0, 0);

    ull Y[NA][CPT], acc[NA][CPT];
    {
        ull bp[CPT];
        #pragma unroll
        for (int p = 0; p < CPT; p++) {
            float2 bv = *(const float2*)&bias[cbase + 64*p + 2*tx];
            bp[p] = pk2f(bv.x, bv.y);
        }
        #pragma unroll
        for (int n = 0; n < NA; n++)
            #pragma unroll
            for (int p = 0; p < CPT; p++) acc[n][p] = bp[p];
    }

    const float* xr = x_s + wq*NA*DIN;
    const ull one2 = 0x3f8000003f800000ULL;  // {1.0f, 1.0f}
    int buf = 0;
    for (int c = 0; c < C5; c++) {
        __syncthreads();
        if (c + 1 < C5) stage(c + 1, buf ^ 1);
        const int mat = c / NCH;
        const int k0  = (c % NCH) * KT;
        if ((c % NCH) == 0) {
            #pragma unroll
            for (int n = 0; n < NA; n++)
                #pragma unroll
                for (int p = 0; p < CPT; p++) Y[n][p] = 0ULL;
        }
        const float* wb = &wt[buf*KT*CT];
        #pragma unroll 8
        for (int kk = 0; kk < KT; kk++) {
            ull xv[NA];
            #pragma unroll
            for (int a = 0; a < NA; a++) xv[a] = pk2(xr[a*DIN + k0 + kk]); // warp bcast
            #pragma unroll
            for (int p = 0; p < CPT; p++) {
                ull wv = *(const ull*)&wb[kk*CT + 64*p + 2*tx];            // LDS.64
                #pragma unroll
                for (int a = 0; a < NA; a++) fma2(Y[a][p], xv[a], wv);
            }
        }
        if ((c % NCH) == NCH - 1) {
            if (mat == 0) {
                #pragma unroll
                for (int n = 0; n < NA; n++)
                    #pragma unroll
                    for (int p = 0; p < CPT; p++) fma2(acc[n][p], Y[n][p], one2);
            } else {
                const int r = mat - 1;
                const float* ar = &adj_s[(wq*NR + r)*NA*NA];
                #pragma unroll
                for (int n = 0; n < NA; n++) {
                    #pragma unroll
                    for (int m = 0; m < NA; m++) {
                        ull av = pk2(ar[n*NA + m]);
                        #pragma unroll
                        for (int p = 0; p < CPT; p++) fma2(acc[n][p], av, Y[m][p]);
                    }
                }
            }
        }
        buf ^= 1;
    }

    // epilogue: store raw + BN statistics
    #pragma unroll
    for (int n = 0; n < NA; n++) {
        size_t rb = ((size_t)(bBase + wq)*NA + n)*DOUT + cbase;
        float s = 0.f, q = 0.f;
        #pragma unroll
        for (int p = 0; p < CPT; p++) {
            *(ull*)&hout[rb + 64*p + 2*tx] = acc[n][p];
            float a, b; up2(acc[n][p], a, b);
            s += a + b;
            q = fmaf(a, a, q); q = fmaf(b, b, q);
        }
        atomicAdd(&red[n],      s);
        atomicAdd(&red[16 + n], q);
    }
    __syncthreads();
    if (tid < NA) {
        atomicAdd(&g_stats[SOUT][0][tid], red[tid]);
        atomicAdd(&g_stats[SOUT][1][tid], red[16 + tid]);
    }
}

// BN(block2) + affine + LeakyReLU + masked atom-sum + FC. One warp per batch.
__global__ void __launch_bounds__(256) readout_kernel(
    const float* __restrict__ mask,
    const float* __restrict__ fcw,
    const float* __restrict__ fcb,
    const float* __restrict__ gamma,
    const float* __restrict__ beta,
    float* __restrict__ out,
    float inv_count)
{
    __shared__ float a_s[NA], c_s[NA], fcs[256];
    int tid = threadIdx.x;
    if (tid < NA) {
        float s = g_stats[2][0][tid];
        float q = g_stats[2][1][tid];
        float mean = s*inv_count;
        float var  = q*inv_count - mean*mean;
        float a = rsqrtf(var + BN_EPS)*gamma[tid];
        a_s[tid] = a;
        c_s[tid] = beta[tid] - mean*a;
    }
    fcs[tid] = fcw[tid];
    __syncthreads();

    int lane = tid & 31, w = tid >> 5;
    int b = blockIdx.x*8 + w;
    float accv = 0.f;
    #pragma unroll
    for (int n = 0; n < NA; n++) {
        float mk = mask[b*NA + n];
        const float* hp = &g_h2[((size_t)b*NA + n)*256];
        float aa = a_s[n], cc = c_s[n];
        #pragma unroll
        for (int j = 0; j < 8; j++) {
            int e = lane + 32*j;
            float v = fmaf(hp[e], aa, cc);
            v = v > 0.f ? v : LRS*v;
            accv = fmaf(v*mk, fcs[e], accv);
        }
    }
    #pragma unroll
    for (int o = 16; o > 0; o >>= 1) accv += __shfl_xor_sync(0xffffffffu, accv, o);
    if (lane == 0) out[b] = accv + fcb[0];
}

extern "C" void kernel_launch(void* const* d_in, const int* in_sizes, int n_in,
                              void* d_out, int out_size)
{
    const float* atom = (const float*)d_in[0];
    const float* adj  = (const float*)d_in[1];
    const float* mask = (const float*)d_in[2];
    const float* ws0=(const float*)d_in[3],  *wr0=(const float*)d_in[4],  *b0=(const float*)d_in[5],  *g0=(const float*)d_in[6],  *be0=(const float*)d_in[7];
    const float* ws1=(const float*)d_in[8],  *wr1=(const float*)d_in[9],  *b1=(const float*)d_in[10], *g1=(const float*)d_in[11], *be1=(const float*)d_in[12];
    const float* ws2=(const float*)d_in[13], *wr2=(const float*)d_in[14], *b2=(const float*)d_in[15], *g2=(const float*)d_in[16], *be2=(const float*)d_in[17];
    const float* fcw=(const float*)d_in[18], *fcb=(const float*)d_in[19];
    float* out = (float*)d_out;

    float *h0, *h1, *h2;
    cudaGetSymbolAddress((void**)&h0, g_h0);
    cudaGetSymbolAddress((void**)&h1, g_h1);
    cudaGetSymbolAddress((void**)&h2, g_h2);

    // smem bytes: ROWS*DIN + 2592 + 2*KT*CT floats
    const int smem0 = (ROWS*5   + 2592 + 2*5*64)  * 4;   // ~14 KB
    const int smem1 = (ROWS*64  + 2592 + 2*32*128)* 4;   // ~62 KB
    const int smem2 = (ROWS*128 + 2592 + 2*32*128)* 4;   // ~80 KB

    cudaFuncSetAttribute((const void*)rgcn_v2<64,128,128,32,true,0,1>,
                         cudaFuncAttributeMaxDynamicSharedMemorySize, smem1);
    cudaFuncSetAttribute((const void*)rgcn_v2<128,256,128,32,true,1,2>,
                         cudaFuncAttributeMaxDynamicSharedMemorySize, smem2);

    const int grid = BATCH/TB;   // 4096

    zero_stats_kernel<<<1,128>>>();
    rgcn_v2<5,64,64,5,false,0,0><<<dim3(grid,1),256,smem0>>>(
        atom, adj, ws0, wr0, b0, g0, be0, h0, 0.f);
    rgcn_v2<64,128,128,32,true,0,1><<<dim3(grid,1),256,smem1>>>(
        h0, adj, ws1, wr1, b1, g0, be0, h1, 1.0f/((float)BATCH*64.0f));
    rgcn_v2<128,256,128,32,true,1,2><<<dim3(grid,2),256,smem2>>>(
        h1, adj, ws2, wr2, b2, g1, be1, h2, 1.0f/((float)BATCH*128.0f));
    readout_kernel<<<grid,256>>>(
        mask, fcw, fcb, g2, be2, out, 1.0f/((float)BATCH*256.0f));
}

// round 4
// speedup vs baseline: 5.1116x; 3.8882x over previous
#include <cuda_runtime.h>
#include <cstdint>
#include <math.h>

#define BATCH 32768
#define NA 9
#define NR 4
#define LRS 0.2f
#define BN_EPS 1e-5f
#define MTOT (BATCH*NA)

// ---- scratch (device globals; no allocs) ----
__device__ float g_h0[(size_t)MTOT*64];
__device__ float g_h1[(size_t)MTOT*128];
__device__ float g_h2[(size_t)MTOT*256];
__device__ float g_x [(size_t)MTOT*640];
__device__ float g_wt[256*640];
__device__ float g_stats[3][2][16];

__global__ void zero_stats_kernel() {
    int i = threadIdx.x;
    if (i < 96) ((float*)g_stats)[i] = 0.0f;
}

// ---------------- helpers ----------------
static __device__ __forceinline__ uint32_t s2u(const void* p){
    uint32_t a;
    asm("{ .reg .u64 t; cvta.to.shared.u64 t, %1; cvt.u32.u64 %0, t; }":"=r"(a):"l"(p));
    return a;
}
static __device__ __forceinline__ float tf32r(float v){
    uint32_t u; asm("cvt.rna.tf32.f32 %0, %1;" : "=r"(u) : "f"(v));
    return __uint_as_float(u);
}
#define CPA16(dst,src) asm volatile("cp.async.cg.shared.global [%0], [%1], 16;"::"r"(dst),"l"(src):"memory")
#define CPA_COMMIT()   asm volatile("cp.async.commit_group;":::"memory")
#define CPA_WAIT(n)    asm volatile("cp.async.wait_group %0;"::"n"(n):"memory")

static __device__ __forceinline__ void mma_tf32(
    float& d0, float& d1, float& d2, float& d3,
    uint32_t a0, uint32_t a1, uint32_t a2, uint32_t a3,
    uint32_t b0, uint32_t b1)
{
    asm volatile(
        "mma.sync.aligned.m16n8k8.row.col.f32.tf32.tf32.f32 "
        "{%0,%1,%2,%3}, {%4,%5,%6,%7}, {%8,%9}, {%0,%1,%2,%3};"
        : "+f"(d0), "+f"(d1), "+f"(d2), "+f"(d3)
        : "r"(a0), "r"(a1), "r"(a2), "r"(a3), "r"(b0), "r"(b1));
}

// ---------------- Wt build: frag-packed, tf32-rounded ----------------
// Bp offset for (n,k): kstep=k/8, kk=k%8, lane=(n%8)*4+(kk&3), half=kk>>2
//   off = ((n/8)*(K5P/8) + kstep)*64 + lane*2 + half
template<int DIN,int DOUT,int K5P>
__global__ void wt_build(const float* __restrict__ ws, const float* __restrict__ wr,
                         float* __restrict__ bp){
    int i = blockIdx.x*256 + threadIdx.x;
    if (i >= DOUT*K5P) return;
    int n = i / K5P, k = i - n*K5P;
    float v = 0.f;
    if (k < DIN) v = ws[k*DOUT + n];
    else if (k < 5*DIN) {
        int r = (k - DIN) / DIN, kk = (k - DIN) - r*DIN;
        v = wr[(size_t)(r*DIN + kk)*DOUT + n];
    }
    int kstep = k >> 3, kk = k & 7;
    int lane = (n & 7)*4 + (kk & 3), half = kk >> 2;
    bp[((size_t)(n >> 3)*(K5P/8) + kstep)*64 + lane*2 + half] = tf32r(v);
}

// ---------------- X build: X = [h_norm | adj_r @ h_norm], tf32-rounded ----------------
template<int DIN, int K5P, bool NORM, int SIN>
__global__ void __launch_bounds__(256) x_build(
    const float* __restrict__ hin, const float* __restrict__ adj,
    const float* __restrict__ gamma, const float* __restrict__ beta,
    float* __restrict__ Xo, float invp)
{
    constexpr int MB = 8;
    __shared__ float h_s[MB*NA*DIN];
    __shared__ float adj_s[MB*NR*NA*NA];
    __shared__ float nrm[32];
    const int tid = threadIdx.x;
    const size_t mb = (size_t)blockIdx.x * MB;
    if (NORM && tid < NA){
        float s = g_stats[SIN][0][tid], q = g_stats[SIN][1][tid];
        float mean = s*invp, var = q*invp - mean*mean;
        float a = rsqrtf(var + BN_EPS) * gamma[tid];
        nrm[tid] = a; nrm[16+tid] = beta[tid] - mean*a;
    }
    __syncthreads();
    for (int i = tid; i < MB*NA*DIN; i += 256){
        float v = hin[mb*NA*DIN + i];
        if (NORM){
            int n = (i/DIN) % NA;
            v = fmaf(v, nrm[n], nrm[16+n]);
            v = v > 0.f ? v : LRS*v;
        }
        h_s[i] = v;
    }
    for (int i = tid; i < MB*NR*NA*NA; i += 256)
        adj_s[i] = adj[mb*NR*NA*NA + i];
    __syncthreads();
    for (int i = tid; i < MB*NA*K5P; i += 256){
        int row = i / K5P, col = i - row*K5P;
        int m = row / NA, n = row - m*NA;
        float v = 0.f;
        if (col < DIN) v = h_s[row*DIN + col];
        else if (col < 5*DIN){
            int r = (col - DIN) / DIN, d = (col - DIN) - r*DIN;
            const float* ar = &adj_s[((m*NR + r)*NA + n)*NA];
            const float* hc = &h_s[m*NA*DIN + d];
            #pragma unroll
            for (int mm = 0; mm < NA; mm++) v = fmaf(ar[mm], hc[mm*DIN], v);
        }
        Xo[mb*NA*K5P + i] = tf32r(v);
    }
}

// ---------------- tf32 mma.sync GEMM: hout = X @ Wt^T + bias (+BN stats) ----------------
// CTA: 128 rows x N cols. 8 warps = 4(M) x 2(N). Warp: 32 x N/2.
// K-chunks of 32, double-buffered cp.async.
template<int N, int NCH, int K5P, int SOUT, int MINCTA>
__global__ void __launch_bounds__(256, MINCTA) gemm_mma(
    const float* __restrict__ X,     // [M,K5P] tf32
    const float* __restrict__ Bp,    // frag-packed weights
    const float* __restrict__ bias,
    float* __restrict__ hout)
{
    constexpr int NT  = N/16;        // n8 tiles per warp
    constexpr int ASZ = 128*36;      // floats per A stage (pad 36)
    constexpr int BSZ = N*32;        // floats per B stage
    extern __shared__ __align__(16) float sm[];
    float* As = sm;                  // [2][ASZ]
    float* Bs = sm + 2*ASZ;          // [2][BSZ]
    __shared__ float red[32];
    __shared__ float bias_s[N];

    const int tid = threadIdx.x, lane = tid & 31, wid = tid >> 5;
    const int warp_m = wid & 3, warp_n = wid >> 2;
    const int mBase = blockIdx.x * 128;
    const uint32_t sA = s2u(As), sB = s2u(Bs);

    if (tid < 32) red[tid] = 0.f;
    for (int i = tid; i < N; i += 256) bias_s[i] = bias[i];

    auto loadA = [&](int kc, int s){
        const float* src = X + (size_t)mBase*K5P + kc*32;
        #pragma unroll
        for (int i = tid; i < 1024; i += 256){
            int row = i >> 3, seg = i & 7;
            CPA16(sA + (s*ASZ + row*36 + seg*4)*4, src + (size_t)row*K5P + seg*4);
        }
    };
    auto loadB = [&](int kc, int s){
        #pragma unroll
        for (int i = tid; i < N*8; i += 256){
            int n8 = i >> 6, rem = i & 63, ks = rem >> 4, q = rem & 15;
            const float* src = Bp + ((size_t)n8*(K5P/8) + kc*4 + ks)*64 + q*4;
            CPA16(sB + (s*BSZ + (n8*4 + ks)*64 + q*4)*4, src);
        }
    };

    loadA(0,0); loadB(0,0); CPA_COMMIT();
    if (NCH > 1){ loadA(1,1); loadB(1,1); CPA_COMMIT(); }

    float c[2][NT][4];
    #pragma unroll
    for (int mt=0; mt<2; mt++)
        #pragma unroll
        for (int j=0;j<NT;j++)
            #pragma unroll
            for (int q=0;q<4;q++) c[mt][j][q] = 0.f;

    const int arow = warp_m*32 + (lane >> 2);
    const int akc  = lane & 3;

    for (int kc = 0; kc < NCH; kc++){
        const int s = kc & 1;
        if (kc < NCH-1) CPA_WAIT(1); else CPA_WAIT(0);
        __syncthreads();
        const uint32_t* Au = (const uint32_t*)(As + s*ASZ);
        const uint32_t* Bu = (const uint32_t*)(Bs + s*BSZ);
        #pragma unroll
        for (int ks = 0; ks < 4; ks++){
            uint32_t a[2][4];
            #pragma unroll
            for (int mt = 0; mt < 2; mt++){
                int r0 = arow + mt*16;
                int k0 = ks*8 + akc;
                a[mt][0] = Au[r0*36 + k0];
                a[mt][1] = Au[(r0+8)*36 + k0];
                a[mt][2] = Au[r0*36 + k0 + 4];
                a[mt][3] = Au[(r0+8)*36 + k0 + 4];
            }
            #pragma unroll
            for (int j = 0; j < NT; j++){
                int n8 = warp_n*NT + j;
                uint32_t b0 = Bu[(n8*4 + ks)*64 + lane*2];
                uint32_t b1 = Bu[(n8*4 + ks)*64 + lane*2 + 1];
                #pragma unroll
                for (int mt = 0; mt < 2; mt++)
                    mma_tf32(c[mt][j][0], c[mt][j][1], c[mt][j][2], c[mt][j][3],
                             a[mt][0], a[mt][1], a[mt][2], a[mt][3], b0, b1);
            }
        }
        __syncthreads();
        if (kc + 2 < NCH){ loadA(kc+2, s); loadB(kc+2, s); CPA_COMMIT(); }
    }

    // epilogue: bias, raw store, BN stats
    #pragma unroll
    for (int mt = 0; mt < 2; mt++){
        #pragma unroll
        for (int half = 0; half < 2; half++){
            int r0   = warp_m*32 + mt*16 + (lane >> 2) + half*8;
            int grow = mBase + r0;
            int an   = grow % NA;
            float ssum = 0.f, qsum = 0.f;
            float* op = &hout[(size_t)grow*N];
            #pragma unroll
            for (int j = 0; j < NT; j++){
                int col = warp_n*(N/2) + j*8 + (lane & 3)*2;
                float v0 = c[mt][j][half*2+0] + bias_s[col];
                float v1 = c[mt][j][half*2+1] + bias_s[col+1];
                float2 st2; st2.x = v0; st2.y = v1;
                *(float2*)(op + col) = st2;
                ssum += v0 + v1;
                qsum = fmaf(v0, v0, qsum); qsum = fmaf(v1, v1, qsum);
            }
            atomicAdd(&red[an],      ssum);
            atomicAdd(&red[16 + an], qsum);
        }
    }
    __syncthreads();
    if (tid < NA){
        atomicAdd(&g_stats[SOUT][0][tid], red[tid]);
        atomicAdd(&g_stats[SOUT][1][tid], red[16 + tid]);
    }
}

// ---------------- readout: BN + act + masked sum + FC ----------------
__global__ void __launch_bounds__(256) readout_kernel(
    const float* __restrict__ mask, const float* __restrict__ fcw,
    const float* __restrict__ fcb,  const float* __restrict__ gamma,
    const float* __restrict__ beta, float* __restrict__ out, float inv_count)
{
    __shared__ float a_s[NA], c_s[NA], fcs[256];
    int tid = threadIdx.x;
    if (tid < NA){
        float s = g_stats[2][0][tid], q = g_stats[2][1][tid];
        float mean = s*inv_count, var = q*inv_count - mean*mean;
        float a = rsqrtf(var + BN_EPS)*gamma[tid];
        a_s[tid] = a; c_s[tid] = beta[tid] - mean*a;
    }
    fcs[tid] = fcw[tid];
    __syncthreads();
    int lane = tid & 31, w = tid >> 5;
    int b = blockIdx.x*8 + w;
    float accv = 0.f;
    #pragma unroll
    for (int n = 0; n < NA; n++){
        float mk = mask[b*NA + n];
        const float* hp = &g_h2[((size_t)b*NA + n)*256];
        float aa = a_s[n], cc = c_s[n];
        #pragma unroll
        for (int j = 0; j < 8; j++){
            int e = lane + 32*j;
            float v = fmaf(hp[e], aa, cc);
            v = v > 0.f ? v : LRS*v;
            accv = fmaf(v*mk, fcs[e], accv);
        }
    }
    #pragma unroll
    for (int o = 16; o > 0; o >>= 1) accv += __shfl_xor_sync(0xffffffffu, accv, o);
    if (lane == 0) out[b] = accv + fcb[0];
}

extern "C" void kernel_launch(void* const* d_in, const int* in_sizes, int n_in,
                              void* d_out, int out_size)
{
    const float* atom = (const float*)d_in[0];
    const float* adj  = (const float*)d_in[1];
    const float* mask = (const float*)d_in[2];
    const float* ws0=(const float*)d_in[3],  *wr0=(const float*)d_in[4],  *b0=(const float*)d_in[5],  *g0=(const float*)d_in[6],  *be0=(const float*)d_in[7];
    const float* ws1=(const float*)d_in[8],  *wr1=(const float*)d_in[9],  *b1=(const float*)d_in[10], *g1=(const float*)d_in[11], *be1=(const float*)d_in[12];
    const float* ws2=(const float*)d_in[13], *wr2=(const float*)d_in[14], *b2=(const float*)d_in[15], *g2=(const float*)d_in[16], *be2=(const float*)d_in[17];
    const float* fcw=(const float*)d_in[18], *fcb=(const float*)d_in[19];
    float* out = (float*)d_out;

    float *h0,*h1,*h2,*xb,*wtb;
    cudaGetSymbolAddress((void**)&h0, g_h0);
    cudaGetSymbolAddress((void**)&h1, g_h1);
    cudaGetSymbolAddress((void**)&h2, g_h2);
    cudaGetSymbolAddress((void**)&xb, g_x);
    cudaGetSymbolAddress((void**)&wtb, g_wt);

    // dynamic smem: (2*ASZ + 2*N*32) * 4 bytes, ASZ = 128*36
    const int sm0 = (2*128*36 + 2*64*32)  * 4;   //  53248
    const int sm1 = (2*128*36 + 2*128*32) * 4;   //  69632
    const int sm2 = (2*128*36 + 2*256*32) * 4;   // 102400
    cudaFuncSetAttribute((const void*)gemm_mma<64,1,32,0,2>,
                         cudaFuncAttributeMaxDynamicSharedMemorySize, sm0);
    cudaFuncSetAttribute((const void*)gemm_mma<128,10,320,1,2>,
                         cudaFuncAttributeMaxDynamicSharedMemorySize, sm1);
    cudaFuncSetAttribute((const void*)gemm_mma<256,20,640,2,1>,
                         cudaFuncAttributeMaxDynamicSharedMemorySize, sm2);

    const int MT128 = MTOT/128;   // 2304

    zero_stats_kernel<<<1,128>>>();

    // block 0: DIN=5, K5P=32, DOUT=64
    wt_build<5,64,32><<<(64*32+255)/256,256>>>(ws0, wr0, wtb);
    x_build<5,32,false,0><<<BATCH/8,256>>>(atom, adj, g0, be0, xb, 0.f);
    gemm_mma<64,1,32,0,2><<<MT128,256,sm0>>>(xb, wtb, b0, h0);

    // block 1: DIN=64, K5P=320, DOUT=128
    wt_build<64,128,320><<<(128*320+255)/256,256>>>(ws1, wr1, wtb);
    x_build<64,320,true,0><<<BATCH/8,256>>>(h0, adj, g0, be0, xb, 1.f/((float)BATCH*64.f));
    gemm_mma<128,10,320,1,2><<<MT128,256,sm1>>>(xb, wtb, b1, h1);

    // block 2: DIN=128, K5P=640, DOUT=256
    wt_build<128,256,640><<<(256*640+255)/256,256>>>(ws2, wr2, wtb);
    x_build<128,640,true,1><<<BATCH/8,256>>>(h1, adj, g1, be1, xb, 1.f/((float)BATCH*128.f));
    gemm_mma<256,20,640,2,1><<<MT128,256,sm2>>>(xb, wtb, b2, h2);

    readout_kernel<<<BATCH/8,256>>>(mask, fcw, fcb, g2, be2, out, 1.f/((float)BATCH*256.f));
}